// round 10
// baseline (speedup 1.0000x reference)
#include <cuda_runtime.h>
#include <cstdint>

#define B    4
#define N    512
#define H    128
#define MID  128
#define OUTD 128
#define ZD   256
#define JT   64
#define BN   (B*N)
#define BIGNUM 1000000.0f
#define NEGINF -3.0e38f

// Scratch (allocation-free rule: device globals)
__device__ float g_s2[BN * MID];
__device__ float g_base[BN * MID];
__device__ float g_agg[BN * MID];

// ---------------------------------------------------------------------------
// helpers
// ---------------------------------------------------------------------------
__device__ __forceinline__ uint32_t smem_u32(const void* p) {
    return (uint32_t)__cvta_generic_to_shared(p);
}
__device__ __forceinline__ void cp16(uint32_t dst, const void* src) {
    asm volatile("cp.async.cg.shared.global [%0], [%1], 16;\n" :: "r"(dst), "l"(src));
}
__device__ __forceinline__ void cp_commit() { asm volatile("cp.async.commit_group;\n" ::); }
template<int NN> __device__ __forceinline__ void cp_wait() {
    asm volatile("cp.async.wait_group %0;\n" :: "n"(NN));
}
__device__ __forceinline__ float tf32r(float x) {
    float y; asm("cvt.rna.tf32.f32 %0, %1;\n" : "=f"(y) : "f"(x)); return y;
}
__device__ __forceinline__ void mma8(float4& d, float a0, float a1, float a2, float a3,
                                     float b0, float b1) {
    uint32_t A0 = __float_as_uint(a0), A1 = __float_as_uint(a1);
    uint32_t A2 = __float_as_uint(a2), A3 = __float_as_uint(a3);
    uint32_t B0 = __float_as_uint(b0), B1 = __float_as_uint(b1);
    asm volatile(
        "mma.sync.aligned.m16n8k8.row.col.f32.tf32.tf32.f32 "
        "{%0,%1,%2,%3},{%4,%5,%6,%7},{%8,%9},{%0,%1,%2,%3};\n"
        : "+f"(d.x), "+f"(d.y), "+f"(d.z), "+f"(d.w)
        : "r"(A0), "r"(A1), "r"(A2), "r"(A3), "r"(B0), "r"(B1));
}

// ---------------------------------------------------------------------------
// Kernel 1: per-node linears (msg_1, msg_2, msg_g folded into base/s2)
// 16 rows per block, 256 threads: thread = 4 consecutive c (float4 weights),
// 2 rows. Coalesced LDG.128 weight stream, high MLP.
// ---------------------------------------------------------------------------
__global__ __launch_bounds__(256) void prep_kernel(
    const float* __restrict__ node, const float* __restrict__ hidden,
    const float* __restrict__ graph,
    const float* __restrict__ Wm1, const float* __restrict__ bm1,
    const float* __restrict__ Wm2, const float* __restrict__ bm2,
    const float* __restrict__ Wmg, const float* __restrict__ bmg,
    const float* __restrict__ bme)
{
    __shared__ float zsm[16][ZD];
    __shared__ float gsm[H];
    const int row0 = blockIdx.x * 16;
    const int b    = row0 / N;
    const int tid  = threadIdx.x;

    for (int idx = tid; idx < 16 * H; idx += 256) {
        int r = idx >> 7, k = idx & 127;
        zsm[r][k]     = node  [(row0 + r) * H + k];
        zsm[r][H + k] = hidden[(row0 + r) * H + k];
    }
    if (tid < H) gsm[tid] = graph[b * H + tid];
    __syncthreads();

    const int q  = tid & 31;
    const int g  = tid >> 5;       // 0..7 -> rows 2g, 2g+1
    const int c4 = q * 4;

    float4 aB[2], aS[2];
#pragma unroll
    for (int r = 0; r < 2; r++) {
        aB[r] = make_float4(0.f, 0.f, 0.f, 0.f);
        aS[r] = make_float4(0.f, 0.f, 0.f, 0.f);
    }

#pragma unroll 4
    for (int k = 0; k < ZD; k++) {
        float4 w1 = *(const float4*)(Wm1 + k * MID + c4);
        float4 w2 = *(const float4*)(Wm2 + k * MID + c4);
#pragma unroll
        for (int r = 0; r < 2; r++) {
            float z = zsm[2 * g + r][k];
            aB[r].x += z * w1.x; aB[r].y += z * w1.y; aB[r].z += z * w1.z; aB[r].w += z * w1.w;
            aS[r].x += z * w2.x; aS[r].y += z * w2.y; aS[r].z += z * w2.z; aS[r].w += z * w2.w;
        }
    }

    float4 mg = make_float4(0.f, 0.f, 0.f, 0.f);
#pragma unroll 4
    for (int k = 0; k < H; k++) {
        float4 wg = *(const float4*)(Wmg + k * MID + c4);
        float gv = gsm[k];
        mg.x += gv * wg.x; mg.y += gv * wg.y; mg.z += gv * wg.z; mg.w += gv * wg.w;
    }

    float4 v1 = *(const float4*)(bm1 + c4);
    float4 vg = *(const float4*)(bmg + c4);
    float4 ve = *(const float4*)(bme + c4);
    float4 v2 = *(const float4*)(bm2 + c4);
    float4 bb = make_float4(mg.x + v1.x + vg.x + ve.x, mg.y + v1.y + vg.y + ve.y,
                            mg.z + v1.z + vg.z + ve.z, mg.w + v1.w + vg.w + ve.w);

#pragma unroll
    for (int r = 0; r < 2; r++) {
        int row = row0 + 2 * g + r;
        float4 ob = make_float4(aB[r].x + bb.x, aB[r].y + bb.y, aB[r].z + bb.z, aB[r].w + bb.w);
        float4 os = make_float4(aS[r].x + v2.x, aS[r].y + v2.y, aS[r].z + v2.z, aS[r].w + v2.w);
        *(float4*)(g_base + row * MID + c4) = ob;
        *(float4*)(g_s2   + row * MID + c4) = os;
    }
}

// ---------------------------------------------------------------------------
// Kernel 2: fused edge-GEMM + masked max, tf32 tensor cores.
// One block (8 warps) per (b, i). Compacts active j, streams 64-row tiles via
// cp.async double buffer, MMA m16n8k8 tf32, max folded into fragment epilogue.
// Warp w: m-pair = w&1 (m-tiles 2mp,2mp+1), n-quad = w>>1 (n-tiles 4nq..4nq+3).
// ---------------------------------------------------------------------------
#define ESTR 132
#define SSTR 136
#define WF_FLOATS (16*16*32*2)                 // 16384
#define ES_FLOATS (2*JT*ESTR)                  // 16896
#define S2_FLOATS (2*JT*SSTR)                  // 17408
#define SMEM_FLOATS (WF_FLOATS + ES_FLOATS + S2_FLOATS + 256)
#define MSG_SMEM_BYTES (SMEM_FLOATS*4 + N*4)

__global__ __launch_bounds__(256, 1) void msg_kernel(
    const float* __restrict__ edge, const int* __restrict__ adj,
    const float* __restrict__ Wme)
{
    extern __shared__ float smem[];
    float* Wf   = smem;                         // fragment-layout W (tf32)
    float* Es   = Wf + WF_FLOATS;               // 2 x [JT][ESTR]
    float* S2s  = Es + ES_FLOATS;               // 2 x [JT][SSTR]
    float* reds = S2s + S2_FLOATS;              // [2][128]
    int*   list = (int*)(reds + 256);           // N ints
    __shared__ int s_cnt;

    const int tid  = threadIdx.x;
    const int lane = tid & 31;
    const int wid  = tid >> 5;
    const int b    = blockIdx.x >> 9;
    const int i    = blockIdx.x & (N - 1);

    // --- W fragments: Wf[((nt*16+ks)*32+lane)*2 + {0,1}] = W[ks*8+l%4(+4)][nt*8+l/4]
    for (int idx = tid; idx < 16 * 16 * 32; idx += 256) {
        int l  = idx & 31, ks = (idx >> 5) & 15, nt = idx >> 9;
        int k0 = ks * 8 + (l & 3);
        int n  = nt * 8 + (l >> 2);
        Wf[idx * 2]     = tf32r(Wme[k0 * MID + n]);
        Wf[idx * 2 + 1] = tf32r(Wme[(k0 + 4) * MID + n]);
    }
    if (tid == 0) s_cnt = 0;
    __syncthreads();

    // --- compact active senders j for column i
    const int* adjcol = adj + (size_t)b * N * N + i;
    for (int j = tid; j < N; j += 256)
        if (adjcol[(size_t)j * N] != 0) list[atomicAdd(&s_cnt, 1)] = j;
    __syncthreads();
    const int cnt = s_cnt;
    const int T   = (cnt + JT - 1) / JT;

    const float* ebase = edge + ((size_t)b * N * N + i) * H;
    const float* s2b   = g_s2 + (size_t)b * N * MID;

    const int mp  = wid & 1;
    const int nq  = wid >> 1;
    const int gid = lane >> 2;
    const int tq  = lane & 3;

    float mx[4][2];
#pragma unroll
    for (int nt = 0; nt < 4; nt++) { mx[nt][0] = NEGINF; mx[nt][1] = NEGINF; }

    // prefetch tile t into buffer t&1 (cp.async)
    auto prefetch = [&](int t) {
        int off   = t * JT;
        int nrows = min(JT, cnt - off);
        float* Eb = Es  + (t & 1) * JT * ESTR;
        float* Sb = S2s + (t & 1) * JT * SSTR;
        for (int c = tid; c < JT * 32; c += 256) {
            int r = c >> 5, k4 = c & 31;
            if (r < nrows) {
                int j = list[off + r];
                cp16(smem_u32(Eb + r * ESTR + k4 * 4), ebase + (size_t)j * N * H + k4 * 4);
                cp16(smem_u32(Sb + r * SSTR + k4 * 4), s2b + (size_t)j * MID + k4 * 4);
            }
        }
        cp_commit();
    };

    if (T > 0) prefetch(0);

    for (int t = 0; t < T; t++) {
        if (t + 1 < T) { prefetch(t + 1); cp_wait<1>(); }
        else           { cp_wait<0>(); }
        __syncthreads();

        const float* Eb = Es  + (t & 1) * JT * ESTR;
        const float* Sb = S2s + (t & 1) * JT * SSTR;

        float4 acc[2][4];
#pragma unroll
        for (int mm = 0; mm < 2; mm++)
#pragma unroll
            for (int nt = 0; nt < 4; nt++)
                acc[mm][nt] = make_float4(0.f, 0.f, 0.f, 0.f);

#pragma unroll 2
        for (int ks = 0; ks < 16; ks++) {
            float a0[2], a1[2], a2[2], a3[2];
#pragma unroll
            for (int mm = 0; mm < 2; mm++) {
                int mt = mp * 2 + mm;
                const float* ap = Eb + (mt * 16 + gid) * ESTR + ks * 8 + tq;
                a0[mm] = ap[0];
                a1[mm] = ap[8 * ESTR];
                a2[mm] = ap[4];
                a3[mm] = ap[8 * ESTR + 4];
            }
#pragma unroll
            for (int nt = 0; nt < 4; nt++) {
                float2 bf = *(const float2*)(Wf + (((nq * 4 + nt) * 16 + ks) * 32 + lane) * 2);
                mma8(acc[0][nt], a0[0], a1[0], a2[0], a3[0], bf.x, bf.y);
                mma8(acc[1][nt], a0[1], a1[1], a2[1], a3[1], bf.x, bf.y);
            }
        }

        // epilogue: add s2 per row, fold into running max (guard padding rows)
        const int off = t * JT;
        const int nrows = min(JT, cnt - off);
#pragma unroll
        for (int mm = 0; mm < 2; mm++) {
            int mt = mp * 2 + mm;
            int r0 = mt * 16 + gid, r1 = r0 + 8;
            bool v0 = r0 < nrows, v1 = r1 < nrows;
#pragma unroll
            for (int nt = 0; nt < 4; nt++) {
                int col = (nq * 4 + nt) * 8 + tq * 2;
                if (v0) {
                    float2 s = *(const float2*)(Sb + r0 * SSTR + col);
                    mx[nt][0] = fmaxf(mx[nt][0], acc[mm][nt].x + s.x);
                    mx[nt][1] = fmaxf(mx[nt][1], acc[mm][nt].y + s.y);
                }
                if (v1) {
                    float2 s = *(const float2*)(Sb + r1 * SSTR + col);
                    mx[nt][0] = fmaxf(mx[nt][0], acc[mm][nt].z + s.x);
                    mx[nt][1] = fmaxf(mx[nt][1], acc[mm][nt].w + s.y);
                }
            }
        }
        __syncthreads();  // protect buffers from next prefetch overwrite
    }

    // reduce max over row-groups within warp (lanes differing in gid)
#pragma unroll
    for (int nt = 0; nt < 4; nt++)
#pragma unroll
        for (int cc = 0; cc < 2; cc++) {
            float v = mx[nt][cc];
            v = fmaxf(v, __shfl_xor_sync(0xffffffffu, v, 4));
            v = fmaxf(v, __shfl_xor_sync(0xffffffffu, v, 8));
            v = fmaxf(v, __shfl_xor_sync(0xffffffffu, v, 16));
            mx[nt][cc] = v;
        }
    if (gid == 0) {
#pragma unroll
        for (int nt = 0; nt < 4; nt++) {
            int col = (nq * 4 + nt) * 8 + tq * 2;
            reds[mp * 128 + col]     = mx[nt][0];
            reds[mp * 128 + col + 1] = mx[nt][1];
        }
    }
    __syncthreads();

    if (tid < MID) {
        float a;
        if (cnt == 0) {
            a = -BIGNUM;
        } else {
            float m  = fmaxf(reds[tid], reds[128 + tid]);
            float bv = g_base[((size_t)b * N + i) * MID + tid];
            a = m + bv;
            if (cnt < N) a = fmaxf(a, -BIGNUM);
        }
        g_agg[((size_t)b * N + i) * MID + tid] = a;
    }
}

// ---------------------------------------------------------------------------
// Kernel 3: output head. ret = relu(z @ W_o1 + b_o1 + agg @ W_o2 + b_o2)
// Same float4-weight structure as prep.
// ---------------------------------------------------------------------------
__global__ __launch_bounds__(256) void out_kernel(
    const float* __restrict__ node, const float* __restrict__ hidden,
    const float* __restrict__ Wo1, const float* __restrict__ bo1,
    const float* __restrict__ Wo2, const float* __restrict__ bo2,
    float* __restrict__ out)
{
    __shared__ float zsm[16][ZD];
    __shared__ float agsm[16][MID];
    const int row0 = blockIdx.x * 16;
    const int tid  = threadIdx.x;

    for (int idx = tid; idx < 16 * H; idx += 256) {
        int r = idx >> 7, k = idx & 127;
        zsm[r][k]     = node  [(row0 + r) * H + k];
        zsm[r][H + k] = hidden[(row0 + r) * H + k];
        agsm[r][k]    = g_agg [(row0 + r) * MID + k];
    }
    __syncthreads();

    const int q  = tid & 31;
    const int g  = tid >> 5;
    const int c4 = q * 4;

    float4 acc[2];
#pragma unroll
    for (int r = 0; r < 2; r++) acc[r] = make_float4(0.f, 0.f, 0.f, 0.f);

#pragma unroll 4
    for (int k = 0; k < ZD; k++) {
        float4 w = *(const float4*)(Wo1 + k * OUTD + c4);
#pragma unroll
        for (int r = 0; r < 2; r++) {
            float z = zsm[2 * g + r][k];
            acc[r].x += z * w.x; acc[r].y += z * w.y; acc[r].z += z * w.z; acc[r].w += z * w.w;
        }
    }
#pragma unroll 4
    for (int k = 0; k < MID; k++) {
        float4 w = *(const float4*)(Wo2 + k * OUTD + c4);
#pragma unroll
        for (int r = 0; r < 2; r++) {
            float z = agsm[2 * g + r][k];
            acc[r].x += z * w.x; acc[r].y += z * w.y; acc[r].z += z * w.z; acc[r].w += z * w.w;
        }
    }
    float4 b1 = *(const float4*)(bo1 + c4);
    float4 b2 = *(const float4*)(bo2 + c4);
#pragma unroll
    for (int r = 0; r < 2; r++) {
        int row = row0 + 2 * g + r;
        float4 o = make_float4(fmaxf(acc[r].x + b1.x + b2.x, 0.f),
                               fmaxf(acc[r].y + b1.y + b2.y, 0.f),
                               fmaxf(acc[r].z + b1.z + b2.z, 0.f),
                               fmaxf(acc[r].w + b1.w + b2.w, 0.f));
        *(float4*)(out + row * OUTD + c4) = o;
    }
}

// ---------------------------------------------------------------------------
extern "C" void kernel_launch(void* const* d_in, const int* in_sizes, int n_in,
                              void* d_out, int out_size)
{
    const float* node   = (const float*)d_in[0];
    const float* edge   = (const float*)d_in[1];
    const float* graph  = (const float*)d_in[2];
    const int*   adj    = (const int*)  d_in[3];
    const float* hidden = (const float*)d_in[4];
    const float* Wm1 = (const float*)d_in[5];
    const float* bm1 = (const float*)d_in[6];
    const float* Wm2 = (const float*)d_in[7];
    const float* bm2 = (const float*)d_in[8];
    const float* Wme = (const float*)d_in[9];
    const float* bme = (const float*)d_in[10];
    const float* Wmg = (const float*)d_in[11];
    const float* bmg = (const float*)d_in[12];
    const float* Wo1 = (const float*)d_in[13];
    const float* bo1 = (const float*)d_in[14];
    const float* Wo2 = (const float*)d_in[15];
    const float* bo2 = (const float*)d_in[16];
    float* out = (float*)d_out;

    static int configured = 0;
    if (!configured) {
        cudaFuncSetAttribute(msg_kernel, cudaFuncAttributeMaxDynamicSharedMemorySize,
                             MSG_SMEM_BYTES);
        configured = 1;
    }

    prep_kernel<<<BN / 16, 256>>>(node, hidden, graph, Wm1, bm1, Wm2, bm2, Wmg, bmg, bme);
    msg_kernel<<<BN, 256, MSG_SMEM_BYTES>>>(edge, adj, Wme);
    out_kernel<<<BN / 16, 256>>>(node, hidden, Wo1, bo1, Wo2, bo2, out);
}

// round 11
// speedup vs baseline: 1.0004x; 1.0004x over previous
#include <cuda_runtime.h>
#include <cstdint>

#define B    4
#define N    512
#define H    128
#define MID  128
#define OUTD 128
#define ZD   256
#define JT   64
#define BN   (B*N)
#define BIGNUM 1000000.0f
#define NEGINF -3.0e38f

// Scratch (allocation-free rule: device globals)
__device__ float g_s2[BN * MID];
__device__ float g_base[BN * MID];
__device__ float g_agg[BN * MID];

// ---------------------------------------------------------------------------
// helpers
// ---------------------------------------------------------------------------
__device__ __forceinline__ uint32_t smem_u32(const void* p) {
    return (uint32_t)__cvta_generic_to_shared(p);
}
__device__ __forceinline__ void cp16(uint32_t dst, const void* src) {
    asm volatile("cp.async.cg.shared.global [%0], [%1], 16;\n" :: "r"(dst), "l"(src));
}
__device__ __forceinline__ void cp_commit() { asm volatile("cp.async.commit_group;\n" ::); }
template<int NN> __device__ __forceinline__ void cp_wait() {
    asm volatile("cp.async.wait_group %0;\n" :: "n"(NN));
}
__device__ __forceinline__ float tf32r(float x) {
    float y; asm("cvt.rna.tf32.f32 %0, %1;\n" : "=f"(y) : "f"(x)); return y;
}
__device__ __forceinline__ void mma8(float4& d, float a0, float a1, float a2, float a3,
                                     float b0, float b1) {
    uint32_t A0 = __float_as_uint(a0), A1 = __float_as_uint(a1);
    uint32_t A2 = __float_as_uint(a2), A3 = __float_as_uint(a3);
    uint32_t B0 = __float_as_uint(b0), B1 = __float_as_uint(b1);
    asm volatile(
        "mma.sync.aligned.m16n8k8.row.col.f32.tf32.tf32.f32 "
        "{%0,%1,%2,%3},{%4,%5,%6,%7},{%8,%9},{%0,%1,%2,%3};\n"
        : "+f"(d.x), "+f"(d.y), "+f"(d.z), "+f"(d.w)
        : "r"(A0), "r"(A1), "r"(A2), "r"(A3), "r"(B0), "r"(B1));
}

// ---------------------------------------------------------------------------
// Kernel 1: per-node linears (msg_1, msg_2, msg_g folded into base/s2)
// 16 rows per block, 256 threads: thread = 4 consecutive c (float4 weights),
// 2 rows. Coalesced LDG.128 weight stream, high MLP.
// ---------------------------------------------------------------------------
__global__ __launch_bounds__(256) void prep_kernel(
    const float* __restrict__ node, const float* __restrict__ hidden,
    const float* __restrict__ graph,
    const float* __restrict__ Wm1, const float* __restrict__ bm1,
    const float* __restrict__ Wm2, const float* __restrict__ bm2,
    const float* __restrict__ Wmg, const float* __restrict__ bmg,
    const float* __restrict__ bme)
{
    __shared__ float zsm[16][ZD];
    __shared__ float gsm[H];
    const int row0 = blockIdx.x * 16;
    const int b    = row0 / N;
    const int tid  = threadIdx.x;

    for (int idx = tid; idx < 16 * H; idx += 256) {
        int r = idx >> 7, k = idx & 127;
        zsm[r][k]     = node  [(row0 + r) * H + k];
        zsm[r][H + k] = hidden[(row0 + r) * H + k];
    }
    if (tid < H) gsm[tid] = graph[b * H + tid];
    __syncthreads();

    const int q  = tid & 31;
    const int g  = tid >> 5;       // 0..7 -> rows 2g, 2g+1
    const int c4 = q * 4;

    float4 aB[2], aS[2];
#pragma unroll
    for (int r = 0; r < 2; r++) {
        aB[r] = make_float4(0.f, 0.f, 0.f, 0.f);
        aS[r] = make_float4(0.f, 0.f, 0.f, 0.f);
    }

#pragma unroll 4
    for (int k = 0; k < ZD; k++) {
        float4 w1 = *(const float4*)(Wm1 + k * MID + c4);
        float4 w2 = *(const float4*)(Wm2 + k * MID + c4);
#pragma unroll
        for (int r = 0; r < 2; r++) {
            float z = zsm[2 * g + r][k];
            aB[r].x += z * w1.x; aB[r].y += z * w1.y; aB[r].z += z * w1.z; aB[r].w += z * w1.w;
            aS[r].x += z * w2.x; aS[r].y += z * w2.y; aS[r].z += z * w2.z; aS[r].w += z * w2.w;
        }
    }

    float4 mg = make_float4(0.f, 0.f, 0.f, 0.f);
#pragma unroll 4
    for (int k = 0; k < H; k++) {
        float4 wg = *(const float4*)(Wmg + k * MID + c4);
        float gv = gsm[k];
        mg.x += gv * wg.x; mg.y += gv * wg.y; mg.z += gv * wg.z; mg.w += gv * wg.w;
    }

    float4 v1 = *(const float4*)(bm1 + c4);
    float4 vg = *(const float4*)(bmg + c4);
    float4 ve = *(const float4*)(bme + c4);
    float4 v2 = *(const float4*)(bm2 + c4);
    float4 bb = make_float4(mg.x + v1.x + vg.x + ve.x, mg.y + v1.y + vg.y + ve.y,
                            mg.z + v1.z + vg.z + ve.z, mg.w + v1.w + vg.w + ve.w);

#pragma unroll
    for (int r = 0; r < 2; r++) {
        int row = row0 + 2 * g + r;
        float4 ob = make_float4(aB[r].x + bb.x, aB[r].y + bb.y, aB[r].z + bb.z, aB[r].w + bb.w);
        float4 os = make_float4(aS[r].x + v2.x, aS[r].y + v2.y, aS[r].z + v2.z, aS[r].w + v2.w);
        *(float4*)(g_base + row * MID + c4) = ob;
        *(float4*)(g_s2   + row * MID + c4) = os;
    }
}

// ---------------------------------------------------------------------------
// Kernel 2: fused edge-GEMM + masked max, tf32 tensor cores.
// One block (8 warps) per (b, i). Compacts active j, streams 64-row tiles via
// cp.async double buffer, MMA m16n8k8 tf32, max folded into fragment epilogue.
// Warp w: m-pair = w&1 (m-tiles 2mp,2mp+1), n-quad = w>>1 (n-tiles 4nq..4nq+3).
// ---------------------------------------------------------------------------
#define ESTR 132
#define SSTR 136
#define WF_FLOATS (16*16*32*2)                 // 16384
#define ES_FLOATS (2*JT*ESTR)                  // 16896
#define S2_FLOATS (2*JT*SSTR)                  // 17408
#define SMEM_FLOATS (WF_FLOATS + ES_FLOATS + S2_FLOATS + 256)
#define MSG_SMEM_BYTES (SMEM_FLOATS*4 + N*4)

__global__ __launch_bounds__(256, 1) void msg_kernel(
    const float* __restrict__ edge, const int* __restrict__ adj,
    const float* __restrict__ Wme)
{
    extern __shared__ float smem[];
    float* Wf   = smem;                         // fragment-layout W (tf32)
    float* Es   = Wf + WF_FLOATS;               // 2 x [JT][ESTR]
    float* S2s  = Es + ES_FLOATS;               // 2 x [JT][SSTR]
    float* reds = S2s + S2_FLOATS;              // [2][128]
    int*   list = (int*)(reds + 256);           // N ints
    __shared__ int s_cnt;

    const int tid  = threadIdx.x;
    const int lane = tid & 31;
    const int wid  = tid >> 5;
    const int b    = blockIdx.x >> 9;
    const int i    = blockIdx.x & (N - 1);

    // --- W fragments: Wf[((nt*16+ks)*32+lane)*2 + {0,1}] = W[ks*8+l%4(+4)][nt*8+l/4]
    for (int idx = tid; idx < 16 * 16 * 32; idx += 256) {
        int l  = idx & 31, ks = (idx >> 5) & 15, nt = idx >> 9;
        int k0 = ks * 8 + (l & 3);
        int n  = nt * 8 + (l >> 2);
        Wf[idx * 2]     = tf32r(Wme[k0 * MID + n]);
        Wf[idx * 2 + 1] = tf32r(Wme[(k0 + 4) * MID + n]);
    }
    if (tid == 0) s_cnt = 0;
    __syncthreads();

    // --- compact active senders j for column i
    const int* adjcol = adj + (size_t)b * N * N + i;
    for (int j = tid; j < N; j += 256)
        if (adjcol[(size_t)j * N] != 0) list[atomicAdd(&s_cnt, 1)] = j;
    __syncthreads();
    const int cnt = s_cnt;
    const int T   = (cnt + JT - 1) / JT;

    const float* ebase = edge + ((size_t)b * N * N + i) * H;
    const float* s2b   = g_s2 + (size_t)b * N * MID;

    const int mp  = wid & 1;
    const int nq  = wid >> 1;
    const int gid = lane >> 2;
    const int tq  = lane & 3;

    float mx[4][2];
#pragma unroll
    for (int nt = 0; nt < 4; nt++) { mx[nt][0] = NEGINF; mx[nt][1] = NEGINF; }

    // prefetch tile t into buffer t&1 (cp.async)
    auto prefetch = [&](int t) {
        int off   = t * JT;
        int nrows = min(JT, cnt - off);
        float* Eb = Es  + (t & 1) * JT * ESTR;
        float* Sb = S2s + (t & 1) * JT * SSTR;
        for (int c = tid; c < JT * 32; c += 256) {
            int r = c >> 5, k4 = c & 31;
            if (r < nrows) {
                int j = list[off + r];
                cp16(smem_u32(Eb + r * ESTR + k4 * 4), ebase + (size_t)j * N * H + k4 * 4);
                cp16(smem_u32(Sb + r * SSTR + k4 * 4), s2b + (size_t)j * MID + k4 * 4);
            }
        }
        cp_commit();
    };

    if (T > 0) prefetch(0);

    for (int t = 0; t < T; t++) {
        if (t + 1 < T) { prefetch(t + 1); cp_wait<1>(); }
        else           { cp_wait<0>(); }
        __syncthreads();

        const float* Eb = Es  + (t & 1) * JT * ESTR;
        const float* Sb = S2s + (t & 1) * JT * SSTR;

        float4 acc[2][4];
#pragma unroll
        for (int mm = 0; mm < 2; mm++)
#pragma unroll
            for (int nt = 0; nt < 4; nt++)
                acc[mm][nt] = make_float4(0.f, 0.f, 0.f, 0.f);

#pragma unroll 2
        for (int ks = 0; ks < 16; ks++) {
            float a0[2], a1[2], a2[2], a3[2];
#pragma unroll
            for (int mm = 0; mm < 2; mm++) {
                int mt = mp * 2 + mm;
                const float* ap = Eb + (mt * 16 + gid) * ESTR + ks * 8 + tq;
                a0[mm] = ap[0];
                a1[mm] = ap[8 * ESTR];
                a2[mm] = ap[4];
                a3[mm] = ap[8 * ESTR + 4];
            }
#pragma unroll
            for (int nt = 0; nt < 4; nt++) {
                float2 bf = *(const float2*)(Wf + (((nq * 4 + nt) * 16 + ks) * 32 + lane) * 2);
                mma8(acc[0][nt], a0[0], a1[0], a2[0], a3[0], bf.x, bf.y);
                mma8(acc[1][nt], a0[1], a1[1], a2[1], a3[1], bf.x, bf.y);
            }
        }

        // epilogue: add s2 per row, fold into running max (guard padding rows)
        const int off = t * JT;
        const int nrows = min(JT, cnt - off);
#pragma unroll
        for (int mm = 0; mm < 2; mm++) {
            int mt = mp * 2 + mm;
            int r0 = mt * 16 + gid, r1 = r0 + 8;
            bool v0 = r0 < nrows, v1 = r1 < nrows;
#pragma unroll
            for (int nt = 0; nt < 4; nt++) {
                int col = (nq * 4 + nt) * 8 + tq * 2;
                if (v0) {
                    float2 s = *(const float2*)(Sb + r0 * SSTR + col);
                    mx[nt][0] = fmaxf(mx[nt][0], acc[mm][nt].x + s.x);
                    mx[nt][1] = fmaxf(mx[nt][1], acc[mm][nt].y + s.y);
                }
                if (v1) {
                    float2 s = *(const float2*)(Sb + r1 * SSTR + col);
                    mx[nt][0] = fmaxf(mx[nt][0], acc[mm][nt].z + s.x);
                    mx[nt][1] = fmaxf(mx[nt][1], acc[mm][nt].w + s.y);
                }
            }
        }
        __syncthreads();  // protect buffers from next prefetch overwrite
    }

    // reduce max over row-groups within warp (lanes differing in gid)
#pragma unroll
    for (int nt = 0; nt < 4; nt++)
#pragma unroll
        for (int cc = 0; cc < 2; cc++) {
            float v = mx[nt][cc];
            v = fmaxf(v, __shfl_xor_sync(0xffffffffu, v, 4));
            v = fmaxf(v, __shfl_xor_sync(0xffffffffu, v, 8));
            v = fmaxf(v, __shfl_xor_sync(0xffffffffu, v, 16));
            mx[nt][cc] = v;
        }
    if (gid == 0) {
#pragma unroll
        for (int nt = 0; nt < 4; nt++) {
            int col = (nq * 4 + nt) * 8 + tq * 2;
            reds[mp * 128 + col]     = mx[nt][0];
            reds[mp * 128 + col + 1] = mx[nt][1];
        }
    }
    __syncthreads();

    if (tid < MID) {
        float a;
        if (cnt == 0) {
            a = -BIGNUM;
        } else {
            float m  = fmaxf(reds[tid], reds[128 + tid]);
            float bv = g_base[((size_t)b * N + i) * MID + tid];
            a = m + bv;
            if (cnt < N) a = fmaxf(a, -BIGNUM);
        }
        g_agg[((size_t)b * N + i) * MID + tid] = a;
    }
}

// ---------------------------------------------------------------------------
// Kernel 3: output head. ret = relu(z @ W_o1 + b_o1 + agg @ W_o2 + b_o2)
// Same float4-weight structure as prep.
// ---------------------------------------------------------------------------
__global__ __launch_bounds__(256) void out_kernel(
    const float* __restrict__ node, const float* __restrict__ hidden,
    const float* __restrict__ Wo1, const float* __restrict__ bo1,
    const float* __restrict__ Wo2, const float* __restrict__ bo2,
    float* __restrict__ out)
{
    __shared__ float zsm[16][ZD];
    __shared__ float agsm[16][MID];
    const int row0 = blockIdx.x * 16;
    const int tid  = threadIdx.x;

    for (int idx = tid; idx < 16 * H; idx += 256) {
        int r = idx >> 7, k = idx & 127;
        zsm[r][k]     = node  [(row0 + r) * H + k];
        zsm[r][H + k] = hidden[(row0 + r) * H + k];
        agsm[r][k]    = g_agg [(row0 + r) * MID + k];
    }
    __syncthreads();

    const int q  = tid & 31;
    const int g  = tid >> 5;
    const int c4 = q * 4;

    float4 acc[2];
#pragma unroll
    for (int r = 0; r < 2; r++) acc[r] = make_float4(0.f, 0.f, 0.f, 0.f);

#pragma unroll 4
    for (int k = 0; k < ZD; k++) {
        float4 w = *(const float4*)(Wo1 + k * OUTD + c4);
#pragma unroll
        for (int r = 0; r < 2; r++) {
            float z = zsm[2 * g + r][k];
            acc[r].x += z * w.x; acc[r].y += z * w.y; acc[r].z += z * w.z; acc[r].w += z * w.w;
        }
    }
#pragma unroll 4
    for (int k = 0; k < MID; k++) {
        float4 w = *(const float4*)(Wo2 + k * OUTD + c4);
#pragma unroll
        for (int r = 0; r < 2; r++) {
            float z = agsm[2 * g + r][k];
            acc[r].x += z * w.x; acc[r].y += z * w.y; acc[r].z += z * w.z; acc[r].w += z * w.w;
        }
    }
    float4 b1 = *(const float4*)(bo1 + c4);
    float4 b2 = *(const float4*)(bo2 + c4);
#pragma unroll
    for (int r = 0; r < 2; r++) {
        int row = row0 + 2 * g + r;
        float4 o = make_float4(fmaxf(acc[r].x + b1.x + b2.x, 0.f),
                               fmaxf(acc[r].y + b1.y + b2.y, 0.f),
                               fmaxf(acc[r].z + b1.z + b2.z, 0.f),
                               fmaxf(acc[r].w + b1.w + b2.w, 0.f));
        *(float4*)(out + row * OUTD + c4) = o;
    }
}

// ---------------------------------------------------------------------------
extern "C" void kernel_launch(void* const* d_in, const int* in_sizes, int n_in,
                              void* d_out, int out_size)
{
    const float* node   = (const float*)d_in[0];
    const float* edge   = (const float*)d_in[1];
    const float* graph  = (const float*)d_in[2];
    const int*   adj    = (const int*)  d_in[3];
    const float* hidden = (const float*)d_in[4];
    const float* Wm1 = (const float*)d_in[5];
    const float* bm1 = (const float*)d_in[6];
    const float* Wm2 = (const float*)d_in[7];
    const float* bm2 = (const float*)d_in[8];
    const float* Wme = (const float*)d_in[9];
    const float* bme = (const float*)d_in[10];
    const float* Wmg = (const float*)d_in[11];
    const float* bmg = (const float*)d_in[12];
    const float* Wo1 = (const float*)d_in[13];
    const float* bo1 = (const float*)d_in[14];
    const float* Wo2 = (const float*)d_in[15];
    const float* bo2 = (const float*)d_in[16];
    float* out = (float*)d_out;

    static int configured = 0;
    if (!configured) {
        cudaFuncSetAttribute(msg_kernel, cudaFuncAttributeMaxDynamicSharedMemorySize,
                             MSG_SMEM_BYTES);
        configured = 1;
    }

    prep_kernel<<<BN / 16, 256>>>(node, hidden, graph, Wm1, bm1, Wm2, bm2, Wmg, bmg, bme);
    msg_kernel<<<BN, 256, MSG_SMEM_BYTES>>>(edge, adj, Wme);
    out_kernel<<<BN / 16, 256>>>(node, hidden, Wo1, bo1, Wo2, bo2, out);
}

// round 12
// speedup vs baseline: 1.0050x; 1.0046x over previous
#include <cuda_runtime.h>
#include <cstdint>

#define B    4
#define N    512
#define H    128
#define MID  128
#define OUTD 128
#define ZD   256
#define JT   64
#define BN   (B*N)
#define BIGNUM 1000000.0f
#define NEGINF -3.0e38f

// Scratch (allocation-free rule: device globals)
__device__ float g_s2[BN * MID];
__device__ float g_base[BN * MID];
__device__ float g_agg[BN * MID];

// ---------------------------------------------------------------------------
// helpers
// ---------------------------------------------------------------------------
__device__ __forceinline__ uint32_t smem_u32(const void* p) {
    return (uint32_t)__cvta_generic_to_shared(p);
}
__device__ __forceinline__ void cp16(uint32_t dst, const void* src) {
    asm volatile("cp.async.cg.shared.global [%0], [%1], 16;\n" :: "r"(dst), "l"(src));
}
__device__ __forceinline__ void cp_commit() { asm volatile("cp.async.commit_group;\n" ::); }
template<int NN> __device__ __forceinline__ void cp_wait() {
    asm volatile("cp.async.wait_group %0;\n" :: "n"(NN));
}
__device__ __forceinline__ float tf32r(float x) {
    float y; asm("cvt.rna.tf32.f32 %0, %1;\n" : "=f"(y) : "f"(x)); return y;
}
__device__ __forceinline__ void mma8(float4& d, float a0, float a1, float a2, float a3,
                                     float b0, float b1) {
    uint32_t A0 = __float_as_uint(a0), A1 = __float_as_uint(a1);
    uint32_t A2 = __float_as_uint(a2), A3 = __float_as_uint(a3);
    uint32_t B0 = __float_as_uint(b0), B1 = __float_as_uint(b1);
    asm volatile(
        "mma.sync.aligned.m16n8k8.row.col.f32.tf32.tf32.f32 "
        "{%0,%1,%2,%3},{%4,%5,%6,%7},{%8,%9},{%0,%1,%2,%3};\n"
        : "+f"(d.x), "+f"(d.y), "+f"(d.z), "+f"(d.w)
        : "r"(A0), "r"(A1), "r"(A2), "r"(A3), "r"(B0), "r"(B1));
}

// ---------------------------------------------------------------------------
// Kernel 1: per-node linears (msg_1, msg_2, msg_g folded into base/s2)
// 16 rows per block, 256 threads: thread = 4 consecutive c (float4 weights),
// 2 rows. Coalesced LDG.128 weight stream, high MLP.
// ---------------------------------------------------------------------------
__global__ __launch_bounds__(256) void prep_kernel(
    const float* __restrict__ node, const float* __restrict__ hidden,
    const float* __restrict__ graph,
    const float* __restrict__ Wm1, const float* __restrict__ bm1,
    const float* __restrict__ Wm2, const float* __restrict__ bm2,
    const float* __restrict__ Wmg, const float* __restrict__ bmg,
    const float* __restrict__ bme)
{
    __shared__ float zsm[16][ZD];
    __shared__ float gsm[H];
    const int row0 = blockIdx.x * 16;
    const int b    = row0 / N;
    const int tid  = threadIdx.x;

    for (int idx = tid; idx < 16 * H; idx += 256) {
        int r = idx >> 7, k = idx & 127;
        zsm[r][k]     = node  [(row0 + r) * H + k];
        zsm[r][H + k] = hidden[(row0 + r) * H + k];
    }
    if (tid < H) gsm[tid] = graph[b * H + tid];
    __syncthreads();

    const int q  = tid & 31;
    const int g  = tid >> 5;       // 0..7 -> rows 2g, 2g+1
    const int c4 = q * 4;

    float4 aB[2], aS[2];
#pragma unroll
    for (int r = 0; r < 2; r++) {
        aB[r] = make_float4(0.f, 0.f, 0.f, 0.f);
        aS[r] = make_float4(0.f, 0.f, 0.f, 0.f);
    }

#pragma unroll 4
    for (int k = 0; k < ZD; k++) {
        float4 w1 = *(const float4*)(Wm1 + k * MID + c4);
        float4 w2 = *(const float4*)(Wm2 + k * MID + c4);
#pragma unroll
        for (int r = 0; r < 2; r++) {
            float z = zsm[2 * g + r][k];
            aB[r].x += z * w1.x; aB[r].y += z * w1.y; aB[r].z += z * w1.z; aB[r].w += z * w1.w;
            aS[r].x += z * w2.x; aS[r].y += z * w2.y; aS[r].z += z * w2.z; aS[r].w += z * w2.w;
        }
    }

    float4 mg = make_float4(0.f, 0.f, 0.f, 0.f);
#pragma unroll 4
    for (int k = 0; k < H; k++) {
        float4 wg = *(const float4*)(Wmg + k * MID + c4);
        float gv = gsm[k];
        mg.x += gv * wg.x; mg.y += gv * wg.y; mg.z += gv * wg.z; mg.w += gv * wg.w;
    }

    float4 v1 = *(const float4*)(bm1 + c4);
    float4 vg = *(const float4*)(bmg + c4);
    float4 ve = *(const float4*)(bme + c4);
    float4 v2 = *(const float4*)(bm2 + c4);
    float4 bb = make_float4(mg.x + v1.x + vg.x + ve.x, mg.y + v1.y + vg.y + ve.y,
                            mg.z + v1.z + vg.z + ve.z, mg.w + v1.w + vg.w + ve.w);

#pragma unroll
    for (int r = 0; r < 2; r++) {
        int row = row0 + 2 * g + r;
        float4 ob = make_float4(aB[r].x + bb.x, aB[r].y + bb.y, aB[r].z + bb.z, aB[r].w + bb.w);
        float4 os = make_float4(aS[r].x + v2.x, aS[r].y + v2.y, aS[r].z + v2.z, aS[r].w + v2.w);
        *(float4*)(g_base + row * MID + c4) = ob;
        *(float4*)(g_s2   + row * MID + c4) = os;
    }
}

// ---------------------------------------------------------------------------
// Kernel 2: fused edge-GEMM + masked max, tf32 tensor cores.
// One block (8 warps) per (b, i). Compacts active j, streams 64-row tiles via
// cp.async double buffer, MMA m16n8k8 tf32, max folded into fragment epilogue.
// Warp w: m-pair = w&1 (m-tiles 2mp,2mp+1), n-quad = w>>1 (n-tiles 4nq..4nq+3).
// ---------------------------------------------------------------------------
#define ESTR 132
#define SSTR 136
#define WF_FLOATS (16*16*32*2)                 // 16384
#define ES_FLOATS (2*JT*ESTR)                  // 16896
#define S2_FLOATS (2*JT*SSTR)                  // 17408
#define SMEM_FLOATS (WF_FLOATS + ES_FLOATS + S2_FLOATS + 256)
#define MSG_SMEM_BYTES (SMEM_FLOATS*4 + N*4)

__global__ __launch_bounds__(256, 1) void msg_kernel(
    const float* __restrict__ edge, const int* __restrict__ adj,
    const float* __restrict__ Wme)
{
    extern __shared__ float smem[];
    float* Wf   = smem;                         // fragment-layout W (tf32)
    float* Es   = Wf + WF_FLOATS;               // 2 x [JT][ESTR]
    float* S2s  = Es + ES_FLOATS;               // 2 x [JT][SSTR]
    float* reds = S2s + S2_FLOATS;              // [2][128]
    int*   list = (int*)(reds + 256);           // N ints
    __shared__ int s_cnt;

    const int tid  = threadIdx.x;
    const int lane = tid & 31;
    const int wid  = tid >> 5;
    const int b    = blockIdx.x >> 9;
    const int i    = blockIdx.x & (N - 1);

    // --- W fragments: Wf[((nt*16+ks)*32+lane)*2 + {0,1}] = W[ks*8+l%4(+4)][nt*8+l/4]
    for (int idx = tid; idx < 16 * 16 * 32; idx += 256) {
        int l  = idx & 31, ks = (idx >> 5) & 15, nt = idx >> 9;
        int k0 = ks * 8 + (l & 3);
        int n  = nt * 8 + (l >> 2);
        Wf[idx * 2]     = tf32r(Wme[k0 * MID + n]);
        Wf[idx * 2 + 1] = tf32r(Wme[(k0 + 4) * MID + n]);
    }
    if (tid == 0) s_cnt = 0;
    __syncthreads();

    // --- compact active senders j for column i
    const int* adjcol = adj + (size_t)b * N * N + i;
    for (int j = tid; j < N; j += 256)
        if (adjcol[(size_t)j * N] != 0) list[atomicAdd(&s_cnt, 1)] = j;
    __syncthreads();
    const int cnt = s_cnt;
    const int T   = (cnt + JT - 1) / JT;

    const float* ebase = edge + ((size_t)b * N * N + i) * H;
    const float* s2b   = g_s2 + (size_t)b * N * MID;

    const int mp  = wid & 1;
    const int nq  = wid >> 1;
    const int gid = lane >> 2;
    const int tq  = lane & 3;

    float mx[4][2];
#pragma unroll
    for (int nt = 0; nt < 4; nt++) { mx[nt][0] = NEGINF; mx[nt][1] = NEGINF; }

    // prefetch tile t into buffer t&1 (cp.async)
    auto prefetch = [&](int t) {
        int off   = t * JT;
        int nrows = min(JT, cnt - off);
        float* Eb = Es  + (t & 1) * JT * ESTR;
        float* Sb = S2s + (t & 1) * JT * SSTR;
        for (int c = tid; c < JT * 32; c += 256) {
            int r = c >> 5, k4 = c & 31;
            if (r < nrows) {
                int j = list[off + r];
                cp16(smem_u32(Eb + r * ESTR + k4 * 4), ebase + (size_t)j * N * H + k4 * 4);
                cp16(smem_u32(Sb + r * SSTR + k4 * 4), s2b + (size_t)j * MID + k4 * 4);
            }
        }
        cp_commit();
    };

    if (T > 0) prefetch(0);

    for (int t = 0; t < T; t++) {
        if (t + 1 < T) { prefetch(t + 1); cp_wait<1>(); }
        else           { cp_wait<0>(); }
        __syncthreads();

        const float* Eb = Es  + (t & 1) * JT * ESTR;
        const float* Sb = S2s + (t & 1) * JT * SSTR;

        float4 acc[2][4];
#pragma unroll
        for (int mm = 0; mm < 2; mm++)
#pragma unroll
            for (int nt = 0; nt < 4; nt++)
                acc[mm][nt] = make_float4(0.f, 0.f, 0.f, 0.f);

#pragma unroll 2
        for (int ks = 0; ks < 16; ks++) {
            float a0[2], a1[2], a2[2], a3[2];
#pragma unroll
            for (int mm = 0; mm < 2; mm++) {
                int mt = mp * 2 + mm;
                const float* ap = Eb + (mt * 16 + gid) * ESTR + ks * 8 + tq;
                a0[mm] = ap[0];
                a1[mm] = ap[8 * ESTR];
                a2[mm] = ap[4];
                a3[mm] = ap[8 * ESTR + 4];
            }
#pragma unroll
            for (int nt = 0; nt < 4; nt++) {
                float2 bf = *(const float2*)(Wf + (((nq * 4 + nt) * 16 + ks) * 32 + lane) * 2);
                mma8(acc[0][nt], a0[0], a1[0], a2[0], a3[0], bf.x, bf.y);
                mma8(acc[1][nt], a0[1], a1[1], a2[1], a3[1], bf.x, bf.y);
            }
        }

        // epilogue: add s2 per row, fold into running max (guard padding rows)
        const int off = t * JT;
        const int nrows = min(JT, cnt - off);
#pragma unroll
        for (int mm = 0; mm < 2; mm++) {
            int mt = mp * 2 + mm;
            int r0 = mt * 16 + gid, r1 = r0 + 8;
            bool v0 = r0 < nrows, v1 = r1 < nrows;
#pragma unroll
            for (int nt = 0; nt < 4; nt++) {
                int col = (nq * 4 + nt) * 8 + tq * 2;
                if (v0) {
                    float2 s = *(const float2*)(Sb + r0 * SSTR + col);
                    mx[nt][0] = fmaxf(mx[nt][0], acc[mm][nt].x + s.x);
                    mx[nt][1] = fmaxf(mx[nt][1], acc[mm][nt].y + s.y);
                }
                if (v1) {
                    float2 s = *(const float2*)(Sb + r1 * SSTR + col);
                    mx[nt][0] = fmaxf(mx[nt][0], acc[mm][nt].z + s.x);
                    mx[nt][1] = fmaxf(mx[nt][1], acc[mm][nt].w + s.y);
                }
            }
        }
        __syncthreads();  // protect buffers from next prefetch overwrite
    }

    // reduce max over row-groups within warp (lanes differing in gid)
#pragma unroll
    for (int nt = 0; nt < 4; nt++)
#pragma unroll
        for (int cc = 0; cc < 2; cc++) {
            float v = mx[nt][cc];
            v = fmaxf(v, __shfl_xor_sync(0xffffffffu, v, 4));
            v = fmaxf(v, __shfl_xor_sync(0xffffffffu, v, 8));
            v = fmaxf(v, __shfl_xor_sync(0xffffffffu, v, 16));
            mx[nt][cc] = v;
        }
    if (gid == 0) {
#pragma unroll
        for (int nt = 0; nt < 4; nt++) {
            int col = (nq * 4 + nt) * 8 + tq * 2;
            reds[mp * 128 + col]     = mx[nt][0];
            reds[mp * 128 + col + 1] = mx[nt][1];
        }
    }
    __syncthreads();

    if (tid < MID) {
        float a;
        if (cnt == 0) {
            a = -BIGNUM;
        } else {
            float m  = fmaxf(reds[tid], reds[128 + tid]);
            float bv = g_base[((size_t)b * N + i) * MID + tid];
            a = m + bv;
            if (cnt < N) a = fmaxf(a, -BIGNUM);
        }
        g_agg[((size_t)b * N + i) * MID + tid] = a;
    }
}

// ---------------------------------------------------------------------------
// Kernel 3: output head. ret = relu(z @ W_o1 + b_o1 + agg @ W_o2 + b_o2)
// Same float4-weight structure as prep.
// ---------------------------------------------------------------------------
__global__ __launch_bounds__(256) void out_kernel(
    const float* __restrict__ node, const float* __restrict__ hidden,
    const float* __restrict__ Wo1, const float* __restrict__ bo1,
    const float* __restrict__ Wo2, const float* __restrict__ bo2,
    float* __restrict__ out)
{
    __shared__ float zsm[16][ZD];
    __shared__ float agsm[16][MID];
    const int row0 = blockIdx.x * 16;
    const int tid  = threadIdx.x;

    for (int idx = tid; idx < 16 * H; idx += 256) {
        int r = idx >> 7, k = idx & 127;
        zsm[r][k]     = node  [(row0 + r) * H + k];
        zsm[r][H + k] = hidden[(row0 + r) * H + k];
        agsm[r][k]    = g_agg [(row0 + r) * MID + k];
    }
    __syncthreads();

    const int q  = tid & 31;
    const int g  = tid >> 5;
    const int c4 = q * 4;

    float4 acc[2];
#pragma unroll
    for (int r = 0; r < 2; r++) acc[r] = make_float4(0.f, 0.f, 0.f, 0.f);

#pragma unroll 4
    for (int k = 0; k < ZD; k++) {
        float4 w = *(const float4*)(Wo1 + k * OUTD + c4);
#pragma unroll
        for (int r = 0; r < 2; r++) {
            float z = zsm[2 * g + r][k];
            acc[r].x += z * w.x; acc[r].y += z * w.y; acc[r].z += z * w.z; acc[r].w += z * w.w;
        }
    }
#pragma unroll 4
    for (int k = 0; k < MID; k++) {
        float4 w = *(const float4*)(Wo2 + k * OUTD + c4);
#pragma unroll
        for (int r = 0; r < 2; r++) {
            float z = agsm[2 * g + r][k];
            acc[r].x += z * w.x; acc[r].y += z * w.y; acc[r].z += z * w.z; acc[r].w += z * w.w;
        }
    }
    float4 b1 = *(const float4*)(bo1 + c4);
    float4 b2 = *(const float4*)(bo2 + c4);
#pragma unroll
    for (int r = 0; r < 2; r++) {
        int row = row0 + 2 * g + r;
        float4 o = make_float4(fmaxf(acc[r].x + b1.x + b2.x, 0.f),
                               fmaxf(acc[r].y + b1.y + b2.y, 0.f),
                               fmaxf(acc[r].z + b1.z + b2.z, 0.f),
                               fmaxf(acc[r].w + b1.w + b2.w, 0.f));
        *(float4*)(out + row * OUTD + c4) = o;
    }
}

// ---------------------------------------------------------------------------
extern "C" void kernel_launch(void* const* d_in, const int* in_sizes, int n_in,
                              void* d_out, int out_size)
{
    const float* node   = (const float*)d_in[0];
    const float* edge   = (const float*)d_in[1];
    const float* graph  = (const float*)d_in[2];
    const int*   adj    = (const int*)  d_in[3];
    const float* hidden = (const float*)d_in[4];
    const float* Wm1 = (const float*)d_in[5];
    const float* bm1 = (const float*)d_in[6];
    const float* Wm2 = (const float*)d_in[7];
    const float* bm2 = (const float*)d_in[8];
    const float* Wme = (const float*)d_in[9];
    const float* bme = (const float*)d_in[10];
    const float* Wmg = (const float*)d_in[11];
    const float* bmg = (const float*)d_in[12];
    const float* Wo1 = (const float*)d_in[13];
    const float* bo1 = (const float*)d_in[14];
    const float* Wo2 = (const float*)d_in[15];
    const float* bo2 = (const float*)d_in[16];
    float* out = (float*)d_out;

    static int configured = 0;
    if (!configured) {
        cudaFuncSetAttribute(msg_kernel, cudaFuncAttributeMaxDynamicSharedMemorySize,
                             MSG_SMEM_BYTES);
        configured = 1;
    }

    prep_kernel<<<BN / 16, 256>>>(node, hidden, graph, Wm1, bm1, Wm2, bm2, Wmg, bmg, bme);
    msg_kernel<<<BN, 256, MSG_SMEM_BYTES>>>(edge, adj, Wme);
    out_kernel<<<BN / 16, 256>>>(node, hidden, Wo1, bo1, Wo2, bo2, out);
}

// round 13
// speedup vs baseline: 1.5683x; 1.5605x over previous
#include <cuda_runtime.h>
#include <cstdint>

#define B    4
#define N    512
#define H    128
#define MID  128
#define OUTD 128
#define ZD   256
#define JT   64
#define BN   (B*N)
#define BIGNUM 1000000.0f
#define NEGINF -3.0e38f

// Scratch (allocation-free rule: device globals)
__device__ float g_s2[BN * MID];
__device__ float g_base[BN * MID];
__device__ float g_agg[BN * MID];

// ---------------------------------------------------------------------------
// helpers
// ---------------------------------------------------------------------------
__device__ __forceinline__ uint32_t smem_u32(const void* p) {
    return (uint32_t)__cvta_generic_to_shared(p);
}
__device__ __forceinline__ void cp16(uint32_t dst, const void* src) {
    asm volatile("cp.async.cg.shared.global [%0], [%1], 16;\n" :: "r"(dst), "l"(src));
}
__device__ __forceinline__ void cp_commit() { asm volatile("cp.async.commit_group;\n" ::); }
template<int NN> __device__ __forceinline__ void cp_wait() {
    asm volatile("cp.async.wait_group %0;\n" :: "n"(NN));
}
__device__ __forceinline__ float tf32r(float x) {
    float y; asm("cvt.rna.tf32.f32 %0, %1;\n" : "=f"(y) : "f"(x)); return y;
}
__device__ __forceinline__ void mma8(float4& d, float a0, float a1, float a2, float a3,
                                     float b0, float b1) {
    uint32_t A0 = __float_as_uint(a0), A1 = __float_as_uint(a1);
    uint32_t A2 = __float_as_uint(a2), A3 = __float_as_uint(a3);
    uint32_t B0 = __float_as_uint(b0), B1 = __float_as_uint(b1);
    asm volatile(
        "mma.sync.aligned.m16n8k8.row.col.f32.tf32.tf32.f32 "
        "{%0,%1,%2,%3},{%4,%5,%6,%7},{%8,%9},{%0,%1,%2,%3};\n"
        : "+f"(d.x), "+f"(d.y), "+f"(d.z), "+f"(d.w)
        : "r"(A0), "r"(A1), "r"(A2), "r"(A3), "r"(B0), "r"(B1));
}

// ---------------------------------------------------------------------------
// Kernel 1: per-node linears. cp.async double-buffered weight staging:
// 8 tiles of 32 k-rows of (Wm1|Wm2) pipelined through SMEM, then 4 tiles of
// Wmg for the graph message. 16 rows/block, 256 threads.
// ---------------------------------------------------------------------------
#define PREP_SMEM_FLOATS (16*ZD + 128 + 2*32*256)
#define PREP_SMEM_BYTES  (PREP_SMEM_FLOATS * 4)

__global__ __launch_bounds__(256) void prep_kernel(
    const float* __restrict__ node, const float* __restrict__ hidden,
    const float* __restrict__ graph,
    const float* __restrict__ Wm1, const float* __restrict__ bm1,
    const float* __restrict__ Wm2, const float* __restrict__ bm2,
    const float* __restrict__ Wmg, const float* __restrict__ bmg,
    const float* __restrict__ bme)
{
    extern __shared__ float sm[];
    float* zsm  = sm;                  // 16 * ZD
    float* gsm  = zsm + 16 * ZD;       // 128
    float* Wbuf = gsm + 128;           // 2 * 32 * 256

    const int row0 = blockIdx.x * 16;
    const int b    = row0 / N;
    const int tid  = threadIdx.x;

    for (int idx = tid; idx < 16 * H; idx += 256) {
        int r = idx >> 7, k = idx & 127;
        zsm[r * ZD + k]     = node  [(row0 + r) * H + k];
        zsm[r * ZD + H + k] = hidden[(row0 + r) * H + k];
    }
    if (tid < H) gsm[tid] = graph[b * H + tid];

    const int q  = tid & 31;
    const int g  = tid >> 5;       // warp id -> rows 2g, 2g+1
    const int c4 = q * 4;

    // prefetch k-tile kt of Wm1|Wm2 into buffer kt&1 (32 rows x 256 floats)
    auto pref_m = [&](int kt) {
        const float* w1 = Wm1 + kt * 32 * MID;
        const float* w2 = Wm2 + kt * 32 * MID;
        float* buf = Wbuf + (kt & 1) * 32 * 256;
        for (int idx = tid; idx < 2048; idx += 256) {
            int r = idx >> 6, f = idx & 63;
            if (f < 32) cp16(smem_u32(buf + r * 256 + f * 4),        w1 + r * MID + f * 4);
            else        cp16(smem_u32(buf + r * 256 + 128 + (f-32)*4), w2 + r * MID + (f-32)*4);
        }
        cp_commit();
    };

    float4 aB[2], aS[2];
#pragma unroll
    for (int r = 0; r < 2; r++) {
        aB[r] = make_float4(0.f, 0.f, 0.f, 0.f);
        aS[r] = make_float4(0.f, 0.f, 0.f, 0.f);
    }

    pref_m(0);
    __syncthreads();   // also covers zsm/gsm fills

    for (int kt = 0; kt < 8; kt++) {
        if (kt < 7) { pref_m(kt + 1); cp_wait<1>(); }
        else        { cp_wait<0>(); }
        __syncthreads();
        const float* buf = Wbuf + (kt & 1) * 32 * 256;
        const int k0 = kt * 32;
#pragma unroll 4
        for (int k = 0; k < 32; k++) {
            float4 w1 = *(const float4*)(buf + k * 256 + c4);
            float4 w2 = *(const float4*)(buf + k * 256 + 128 + c4);
#pragma unroll
            for (int r = 0; r < 2; r++) {
                float z = zsm[(2 * g + r) * ZD + k0 + k];
                aB[r].x += z * w1.x; aB[r].y += z * w1.y; aB[r].z += z * w1.z; aB[r].w += z * w1.w;
                aS[r].x += z * w2.x; aS[r].y += z * w2.y; aS[r].z += z * w2.z; aS[r].w += z * w2.w;
            }
        }
        __syncthreads();   // buffer reuse guard
    }

    // graph message: pipeline Wmg in 4 tiles of 32 rows x 128 floats
    auto pref_g = [&](int kt) {
        const float* wg = Wmg + kt * 32 * MID;
        float* buf = Wbuf + (kt & 1) * 32 * 128;
        for (int idx = tid; idx < 1024; idx += 256) {
            int r = idx >> 5, f = idx & 31;
            cp16(smem_u32(buf + r * 128 + f * 4), wg + r * MID + f * 4);
        }
        cp_commit();
    };

    float4 mg = make_float4(0.f, 0.f, 0.f, 0.f);
    pref_g(0);
    for (int kt = 0; kt < 4; kt++) {
        if (kt < 3) { pref_g(kt + 1); cp_wait<1>(); }
        else        { cp_wait<0>(); }
        __syncthreads();
        const float* buf = Wbuf + (kt & 1) * 32 * 128;
        const int k0 = kt * 32;
#pragma unroll 4
        for (int k = 0; k < 32; k++) {
            float gv = gsm[k0 + k];
            float4 wg = *(const float4*)(buf + k * 128 + c4);
            mg.x += gv * wg.x; mg.y += gv * wg.y; mg.z += gv * wg.z; mg.w += gv * wg.w;
        }
        __syncthreads();
    }

    float4 v1 = *(const float4*)(bm1 + c4);
    float4 vg = *(const float4*)(bmg + c4);
    float4 ve = *(const float4*)(bme + c4);
    float4 v2 = *(const float4*)(bm2 + c4);
    float4 bb = make_float4(mg.x + v1.x + vg.x + ve.x, mg.y + v1.y + vg.y + ve.y,
                            mg.z + v1.z + vg.z + ve.z, mg.w + v1.w + vg.w + ve.w);

#pragma unroll
    for (int r = 0; r < 2; r++) {
        int row = row0 + 2 * g + r;
        float4 ob = make_float4(aB[r].x + bb.x, aB[r].y + bb.y, aB[r].z + bb.z, aB[r].w + bb.w);
        float4 os = make_float4(aS[r].x + v2.x, aS[r].y + v2.y, aS[r].z + v2.z, aS[r].w + v2.w);
        *(float4*)(g_base + row * MID + c4) = ob;
        *(float4*)(g_s2   + row * MID + c4) = os;
    }
}

// ---------------------------------------------------------------------------
// Kernel 2: fused edge-GEMM + masked max, tf32 tensor cores. (unchanged)
// ---------------------------------------------------------------------------
#define ESTR 132
#define SSTR 136
#define WF_FLOATS (16*16*32*2)
#define ES_FLOATS (2*JT*ESTR)
#define S2_FLOATS (2*JT*SSTR)
#define SMEM_FLOATS (WF_FLOATS + ES_FLOATS + S2_FLOATS + 256)
#define MSG_SMEM_BYTES (SMEM_FLOATS*4 + N*4)

__global__ __launch_bounds__(256, 1) void msg_kernel(
    const float* __restrict__ edge, const int* __restrict__ adj,
    const float* __restrict__ Wme)
{
    extern __shared__ float smem[];
    float* Wf   = smem;
    float* Es   = Wf + WF_FLOATS;
    float* S2s  = Es + ES_FLOATS;
    float* reds = S2s + S2_FLOATS;
    int*   list = (int*)(reds + 256);
    __shared__ int s_cnt;

    const int tid  = threadIdx.x;
    const int lane = tid & 31;
    const int wid  = tid >> 5;
    const int b    = blockIdx.x >> 9;
    const int i    = blockIdx.x & (N - 1);

    for (int idx = tid; idx < 16 * 16 * 32; idx += 256) {
        int l  = idx & 31, ks = (idx >> 5) & 15, nt = idx >> 9;
        int k0 = ks * 8 + (l & 3);
        int n  = nt * 8 + (l >> 2);
        Wf[idx * 2]     = tf32r(Wme[k0 * MID + n]);
        Wf[idx * 2 + 1] = tf32r(Wme[(k0 + 4) * MID + n]);
    }
    if (tid == 0) s_cnt = 0;
    __syncthreads();

    const int* adjcol = adj + (size_t)b * N * N + i;
    for (int j = tid; j < N; j += 256)
        if (adjcol[(size_t)j * N] != 0) list[atomicAdd(&s_cnt, 1)] = j;
    __syncthreads();
    const int cnt = s_cnt;
    const int T   = (cnt + JT - 1) / JT;

    const float* ebase = edge + ((size_t)b * N * N + i) * H;
    const float* s2b   = g_s2 + (size_t)b * N * MID;

    const int mp  = wid & 1;
    const int nq  = wid >> 1;
    const int gid = lane >> 2;
    const int tq  = lane & 3;

    float mx[4][2];
#pragma unroll
    for (int nt = 0; nt < 4; nt++) { mx[nt][0] = NEGINF; mx[nt][1] = NEGINF; }

    auto prefetch = [&](int t) {
        int off   = t * JT;
        int nrows = min(JT, cnt - off);
        float* Eb = Es  + (t & 1) * JT * ESTR;
        float* Sb = S2s + (t & 1) * JT * SSTR;
        for (int c = tid; c < JT * 32; c += 256) {
            int r = c >> 5, k4 = c & 31;
            if (r < nrows) {
                int j = list[off + r];
                cp16(smem_u32(Eb + r * ESTR + k4 * 4), ebase + (size_t)j * N * H + k4 * 4);
                cp16(smem_u32(Sb + r * SSTR + k4 * 4), s2b + (size_t)j * MID + k4 * 4);
            }
        }
        cp_commit();
    };

    if (T > 0) prefetch(0);

    for (int t = 0; t < T; t++) {
        if (t + 1 < T) { prefetch(t + 1); cp_wait<1>(); }
        else           { cp_wait<0>(); }
        __syncthreads();

        const float* Eb = Es  + (t & 1) * JT * ESTR;
        const float* Sb = S2s + (t & 1) * JT * SSTR;

        float4 acc[2][4];
#pragma unroll
        for (int mm = 0; mm < 2; mm++)
#pragma unroll
            for (int nt = 0; nt < 4; nt++)
                acc[mm][nt] = make_float4(0.f, 0.f, 0.f, 0.f);

#pragma unroll 2
        for (int ks = 0; ks < 16; ks++) {
            float a0[2], a1[2], a2[2], a3[2];
#pragma unroll
            for (int mm = 0; mm < 2; mm++) {
                int mt = mp * 2 + mm;
                const float* ap = Eb + (mt * 16 + gid) * ESTR + ks * 8 + tq;
                a0[mm] = ap[0];
                a1[mm] = ap[8 * ESTR];
                a2[mm] = ap[4];
                a3[mm] = ap[8 * ESTR + 4];
            }
#pragma unroll
            for (int nt = 0; nt < 4; nt++) {
                float2 bf = *(const float2*)(Wf + (((nq * 4 + nt) * 16 + ks) * 32 + lane) * 2);
                mma8(acc[0][nt], a0[0], a1[0], a2[0], a3[0], bf.x, bf.y);
                mma8(acc[1][nt], a0[1], a1[1], a2[1], a3[1], bf.x, bf.y);
            }
        }

        const int off = t * JT;
        const int nrows = min(JT, cnt - off);
#pragma unroll
        for (int mm = 0; mm < 2; mm++) {
            int mt = mp * 2 + mm;
            int r0 = mt * 16 + gid, r1 = r0 + 8;
            bool v0 = r0 < nrows, v1 = r1 < nrows;
#pragma unroll
            for (int nt = 0; nt < 4; nt++) {
                int col = (nq * 4 + nt) * 8 + tq * 2;
                if (v0) {
                    float2 s = *(const float2*)(Sb + r0 * SSTR + col);
                    mx[nt][0] = fmaxf(mx[nt][0], acc[mm][nt].x + s.x);
                    mx[nt][1] = fmaxf(mx[nt][1], acc[mm][nt].y + s.y);
                }
                if (v1) {
                    float2 s = *(const float2*)(Sb + r1 * SSTR + col);
                    mx[nt][0] = fmaxf(mx[nt][0], acc[mm][nt].z + s.x);
                    mx[nt][1] = fmaxf(mx[nt][1], acc[mm][nt].w + s.y);
                }
            }
        }
        __syncthreads();
    }

#pragma unroll
    for (int nt = 0; nt < 4; nt++)
#pragma unroll
        for (int cc = 0; cc < 2; cc++) {
            float v = mx[nt][cc];
            v = fmaxf(v, __shfl_xor_sync(0xffffffffu, v, 4));
            v = fmaxf(v, __shfl_xor_sync(0xffffffffu, v, 8));
            v = fmaxf(v, __shfl_xor_sync(0xffffffffu, v, 16));
            mx[nt][cc] = v;
        }
    if (gid == 0) {
#pragma unroll
        for (int nt = 0; nt < 4; nt++) {
            int col = (nq * 4 + nt) * 8 + tq * 2;
            reds[mp * 128 + col]     = mx[nt][0];
            reds[mp * 128 + col + 1] = mx[nt][1];
        }
    }
    __syncthreads();

    if (tid < MID) {
        float a;
        if (cnt == 0) {
            a = -BIGNUM;
        } else {
            float m  = fmaxf(reds[tid], reds[128 + tid]);
            float bv = g_base[((size_t)b * N + i) * MID + tid];
            a = m + bv;
            if (cnt < N) a = fmaxf(a, -BIGNUM);
        }
        g_agg[((size_t)b * N + i) * MID + tid] = a;
    }
}

// ---------------------------------------------------------------------------
// Kernel 3: output head with cp.async pipelined weights.
// 12 tiles of 32 k-rows: tiles 0-7 = Wo1 (k over z), tiles 8-11 = Wo2 (k over agg).
// ---------------------------------------------------------------------------
#define OUT_SMEM_FLOATS (16*ZD + 16*MID + 2*32*128)
#define OUT_SMEM_BYTES  (OUT_SMEM_FLOATS * 4)

__global__ __launch_bounds__(256) void out_kernel(
    const float* __restrict__ node, const float* __restrict__ hidden,
    const float* __restrict__ Wo1, const float* __restrict__ bo1,
    const float* __restrict__ Wo2, const float* __restrict__ bo2,
    float* __restrict__ out)
{
    extern __shared__ float sm[];
    float* zsm  = sm;                    // 16 * ZD
    float* agsm = zsm + 16 * ZD;         // 16 * MID
    float* Wbuf = agsm + 16 * MID;       // 2 * 32 * 128

    const int row0 = blockIdx.x * 16;
    const int tid  = threadIdx.x;

    for (int idx = tid; idx < 16 * H; idx += 256) {
        int r = idx >> 7, k = idx & 127;
        zsm[r * ZD + k]      = node  [(row0 + r) * H + k];
        zsm[r * ZD + H + k]  = hidden[(row0 + r) * H + k];
        agsm[r * MID + k]    = g_agg [(row0 + r) * MID + k];
    }

    const int q  = tid & 31;
    const int g  = tid >> 5;
    const int c4 = q * 4;

    auto pref = [&](int t) {
        const float* src = (t < 8) ? (Wo1 + t * 32 * OUTD) : (Wo2 + (t - 8) * 32 * OUTD);
        float* buf = Wbuf + (t & 1) * 32 * 128;
        for (int idx = tid; idx < 1024; idx += 256) {
            int r = idx >> 5, f = idx & 31;
            cp16(smem_u32(buf + r * 128 + f * 4), src + r * OUTD + f * 4);
        }
        cp_commit();
    };

    float4 acc[2];
#pragma unroll
    for (int r = 0; r < 2; r++) acc[r] = make_float4(0.f, 0.f, 0.f, 0.f);

    pref(0);
    __syncthreads();   // covers zsm/agsm fill

    for (int t = 0; t < 12; t++) {
        if (t < 11) { pref(t + 1); cp_wait<1>(); }
        else        { cp_wait<0>(); }
        __syncthreads();
        const float* buf = Wbuf + (t & 1) * 32 * 128;
        const float* act = (t < 8) ? (zsm + (t * 32)) : (agsm + ((t - 8) * 32));
        const int astr = (t < 8) ? ZD : MID;
#pragma unroll 4
        for (int k = 0; k < 32; k++) {
            float4 w = *(const float4*)(buf + k * 128 + c4);
#pragma unroll
            for (int r = 0; r < 2; r++) {
                float z = act[(2 * g + r) * astr + k];
                acc[r].x += z * w.x; acc[r].y += z * w.y; acc[r].z += z * w.z; acc[r].w += z * w.w;
            }
        }
        __syncthreads();
    }

    float4 b1 = *(const float4*)(bo1 + c4);
    float4 b2 = *(const float4*)(bo2 + c4);
#pragma unroll
    for (int r = 0; r < 2; r++) {
        int row = row0 + 2 * g + r;
        float4 o = make_float4(fmaxf(acc[r].x + b1.x + b2.x, 0.f),
                               fmaxf(acc[r].y + b1.y + b2.y, 0.f),
                               fmaxf(acc[r].z + b1.z + b2.z, 0.f),
                               fmaxf(acc[r].w + b1.w + b2.w, 0.f));
        *(float4*)(out + row * OUTD + c4) = o;
    }
}

// ---------------------------------------------------------------------------
extern "C" void kernel_launch(void* const* d_in, const int* in_sizes, int n_in,
                              void* d_out, int out_size)
{
    const float* node   = (const float*)d_in[0];
    const float* edge   = (const float*)d_in[1];
    const float* graph  = (const float*)d_in[2];
    const int*   adj    = (const int*)  d_in[3];
    const float* hidden = (const float*)d_in[4];
    const float* Wm1 = (const float*)d_in[5];
    const float* bm1 = (const float*)d_in[6];
    const float* Wm2 = (const float*)d_in[7];
    const float* bm2 = (const float*)d_in[8];
    const float* Wme = (const float*)d_in[9];
    const float* bme = (const float*)d_in[10];
    const float* Wmg = (const float*)d_in[11];
    const float* bmg = (const float*)d_in[12];
    const float* Wo1 = (const float*)d_in[13];
    const float* bo1 = (const float*)d_in[14];
    const float* Wo2 = (const float*)d_in[15];
    const float* bo2 = (const float*)d_in[16];
    float* out = (float*)d_out;

    static int configured = 0;
    if (!configured) {
        cudaFuncSetAttribute(msg_kernel,  cudaFuncAttributeMaxDynamicSharedMemorySize, MSG_SMEM_BYTES);
        cudaFuncSetAttribute(prep_kernel, cudaFuncAttributeMaxDynamicSharedMemorySize, PREP_SMEM_BYTES);
        cudaFuncSetAttribute(out_kernel,  cudaFuncAttributeMaxDynamicSharedMemorySize, OUT_SMEM_BYTES);
        configured = 1;
    }

    prep_kernel<<<BN / 16, 256, PREP_SMEM_BYTES>>>(node, hidden, graph,
                                                   Wm1, bm1, Wm2, bm2, Wmg, bmg, bme);
    msg_kernel<<<BN, 256, MSG_SMEM_BYTES>>>(edge, adj, Wme);
    out_kernel<<<BN / 16, 256, OUT_SMEM_BYTES>>>(node, hidden, Wo1, bo1, Wo2, bo2, out);
}

// round 14
// speedup vs baseline: 1.5793x; 1.0070x over previous
#include <cuda_runtime.h>
#include <cstdint>

#define B    4
#define N    512
#define H    128
#define MID  128
#define OUTD 128
#define ZD   256
#define JT   64
#define BN   (B*N)
#define BIGNUM 1000000.0f
#define NEGINF -3.0e38f

// Scratch (allocation-free rule: device globals)
__device__ float g_s2[BN * MID];
__device__ float g_base[BN * MID];
__device__ float g_agg[BN * MID];

// ---------------------------------------------------------------------------
// helpers
// ---------------------------------------------------------------------------
__device__ __forceinline__ uint32_t smem_u32(const void* p) {
    return (uint32_t)__cvta_generic_to_shared(p);
}
__device__ __forceinline__ void cp16(uint32_t dst, const void* src) {
    asm volatile("cp.async.cg.shared.global [%0], [%1], 16;\n" :: "r"(dst), "l"(src));
}
__device__ __forceinline__ void cp_commit() { asm volatile("cp.async.commit_group;\n" ::); }
template<int NN> __device__ __forceinline__ void cp_wait() {
    asm volatile("cp.async.wait_group %0;\n" :: "n"(NN));
}
__device__ __forceinline__ float tf32r(float x) {
    float y; asm("cvt.rna.tf32.f32 %0, %1;\n" : "=f"(y) : "f"(x)); return y;
}
__device__ __forceinline__ void mma8(float4& d, float a0, float a1, float a2, float a3,
                                     float b0, float b1) {
    uint32_t A0 = __float_as_uint(a0), A1 = __float_as_uint(a1);
    uint32_t A2 = __float_as_uint(a2), A3 = __float_as_uint(a3);
    uint32_t B0 = __float_as_uint(b0), B1 = __float_as_uint(b1);
    asm volatile(
        "mma.sync.aligned.m16n8k8.row.col.f32.tf32.tf32.f32 "
        "{%0,%1,%2,%3},{%4,%5,%6,%7},{%8,%9},{%0,%1,%2,%3};\n"
        : "+f"(d.x), "+f"(d.y), "+f"(d.z), "+f"(d.w)
        : "r"(A0), "r"(A1), "r"(A2), "r"(A3), "r"(B0), "r"(B1));
}

// ---------------------------------------------------------------------------
// Kernel 1: per-node linears. cp.async double-buffered weight staging:
// 8 tiles of 32 k-rows of (Wm1|Wm2) pipelined through SMEM, then 4 tiles of
// Wmg for the graph message. 16 rows/block, 256 threads.
// ---------------------------------------------------------------------------
#define PREP_SMEM_FLOATS (16*ZD + 128 + 2*32*256)
#define PREP_SMEM_BYTES  (PREP_SMEM_FLOATS * 4)

__global__ __launch_bounds__(256) void prep_kernel(
    const float* __restrict__ node, const float* __restrict__ hidden,
    const float* __restrict__ graph,
    const float* __restrict__ Wm1, const float* __restrict__ bm1,
    const float* __restrict__ Wm2, const float* __restrict__ bm2,
    const float* __restrict__ Wmg, const float* __restrict__ bmg,
    const float* __restrict__ bme)
{
    extern __shared__ float sm[];
    float* zsm  = sm;                  // 16 * ZD
    float* gsm  = zsm + 16 * ZD;       // 128
    float* Wbuf = gsm + 128;           // 2 * 32 * 256

    const int row0 = blockIdx.x * 16;
    const int b    = row0 / N;
    const int tid  = threadIdx.x;

    for (int idx = tid; idx < 16 * H; idx += 256) {
        int r = idx >> 7, k = idx & 127;
        zsm[r * ZD + k]     = node  [(row0 + r) * H + k];
        zsm[r * ZD + H + k] = hidden[(row0 + r) * H + k];
    }
    if (tid < H) gsm[tid] = graph[b * H + tid];

    const int q  = tid & 31;
    const int g  = tid >> 5;       // warp id -> rows 2g, 2g+1
    const int c4 = q * 4;

    // prefetch k-tile kt of Wm1|Wm2 into buffer kt&1 (32 rows x 256 floats)
    auto pref_m = [&](int kt) {
        const float* w1 = Wm1 + kt * 32 * MID;
        const float* w2 = Wm2 + kt * 32 * MID;
        float* buf = Wbuf + (kt & 1) * 32 * 256;
        for (int idx = tid; idx < 2048; idx += 256) {
            int r = idx >> 6, f = idx & 63;
            if (f < 32) cp16(smem_u32(buf + r * 256 + f * 4),        w1 + r * MID + f * 4);
            else        cp16(smem_u32(buf + r * 256 + 128 + (f-32)*4), w2 + r * MID + (f-32)*4);
        }
        cp_commit();
    };

    float4 aB[2], aS[2];
#pragma unroll
    for (int r = 0; r < 2; r++) {
        aB[r] = make_float4(0.f, 0.f, 0.f, 0.f);
        aS[r] = make_float4(0.f, 0.f, 0.f, 0.f);
    }

    pref_m(0);
    __syncthreads();   // also covers zsm/gsm fills

    for (int kt = 0; kt < 8; kt++) {
        if (kt < 7) { pref_m(kt + 1); cp_wait<1>(); }
        else        { cp_wait<0>(); }
        __syncthreads();
        const float* buf = Wbuf + (kt & 1) * 32 * 256;
        const int k0 = kt * 32;
#pragma unroll 4
        for (int k = 0; k < 32; k++) {
            float4 w1 = *(const float4*)(buf + k * 256 + c4);
            float4 w2 = *(const float4*)(buf + k * 256 + 128 + c4);
#pragma unroll
            for (int r = 0; r < 2; r++) {
                float z = zsm[(2 * g + r) * ZD + k0 + k];
                aB[r].x += z * w1.x; aB[r].y += z * w1.y; aB[r].z += z * w1.z; aB[r].w += z * w1.w;
                aS[r].x += z * w2.x; aS[r].y += z * w2.y; aS[r].z += z * w2.z; aS[r].w += z * w2.w;
            }
        }
        __syncthreads();   // buffer reuse guard
    }

    // graph message: pipeline Wmg in 4 tiles of 32 rows x 128 floats
    auto pref_g = [&](int kt) {
        const float* wg = Wmg + kt * 32 * MID;
        float* buf = Wbuf + (kt & 1) * 32 * 128;
        for (int idx = tid; idx < 1024; idx += 256) {
            int r = idx >> 5, f = idx & 31;
            cp16(smem_u32(buf + r * 128 + f * 4), wg + r * MID + f * 4);
        }
        cp_commit();
    };

    float4 mg = make_float4(0.f, 0.f, 0.f, 0.f);
    pref_g(0);
    for (int kt = 0; kt < 4; kt++) {
        if (kt < 3) { pref_g(kt + 1); cp_wait<1>(); }
        else        { cp_wait<0>(); }
        __syncthreads();
        const float* buf = Wbuf + (kt & 1) * 32 * 128;
        const int k0 = kt * 32;
#pragma unroll 4
        for (int k = 0; k < 32; k++) {
            float gv = gsm[k0 + k];
            float4 wg = *(const float4*)(buf + k * 128 + c4);
            mg.x += gv * wg.x; mg.y += gv * wg.y; mg.z += gv * wg.z; mg.w += gv * wg.w;
        }
        __syncthreads();
    }

    float4 v1 = *(const float4*)(bm1 + c4);
    float4 vg = *(const float4*)(bmg + c4);
    float4 ve = *(const float4*)(bme + c4);
    float4 v2 = *(const float4*)(bm2 + c4);
    float4 bb = make_float4(mg.x + v1.x + vg.x + ve.x, mg.y + v1.y + vg.y + ve.y,
                            mg.z + v1.z + vg.z + ve.z, mg.w + v1.w + vg.w + ve.w);

#pragma unroll
    for (int r = 0; r < 2; r++) {
        int row = row0 + 2 * g + r;
        float4 ob = make_float4(aB[r].x + bb.x, aB[r].y + bb.y, aB[r].z + bb.z, aB[r].w + bb.w);
        float4 os = make_float4(aS[r].x + v2.x, aS[r].y + v2.y, aS[r].z + v2.z, aS[r].w + v2.w);
        *(float4*)(g_base + row * MID + c4) = ob;
        *(float4*)(g_s2   + row * MID + c4) = os;
    }
}

// ---------------------------------------------------------------------------
// Kernel 2: fused edge-GEMM + masked max, tf32 tensor cores. (unchanged)
// ---------------------------------------------------------------------------
#define ESTR 132
#define SSTR 136
#define WF_FLOATS (16*16*32*2)
#define ES_FLOATS (2*JT*ESTR)
#define S2_FLOATS (2*JT*SSTR)
#define SMEM_FLOATS (WF_FLOATS + ES_FLOATS + S2_FLOATS + 256)
#define MSG_SMEM_BYTES (SMEM_FLOATS*4 + N*4)

__global__ __launch_bounds__(256, 1) void msg_kernel(
    const float* __restrict__ edge, const int* __restrict__ adj,
    const float* __restrict__ Wme)
{
    extern __shared__ float smem[];
    float* Wf   = smem;
    float* Es   = Wf + WF_FLOATS;
    float* S2s  = Es + ES_FLOATS;
    float* reds = S2s + S2_FLOATS;
    int*   list = (int*)(reds + 256);
    __shared__ int s_cnt;

    const int tid  = threadIdx.x;
    const int lane = tid & 31;
    const int wid  = tid >> 5;
    const int b    = blockIdx.x >> 9;
    const int i    = blockIdx.x & (N - 1);

    for (int idx = tid; idx < 16 * 16 * 32; idx += 256) {
        int l  = idx & 31, ks = (idx >> 5) & 15, nt = idx >> 9;
        int k0 = ks * 8 + (l & 3);
        int n  = nt * 8 + (l >> 2);
        Wf[idx * 2]     = tf32r(Wme[k0 * MID + n]);
        Wf[idx * 2 + 1] = tf32r(Wme[(k0 + 4) * MID + n]);
    }
    if (tid == 0) s_cnt = 0;
    __syncthreads();

    const int* adjcol = adj + (size_t)b * N * N + i;
    for (int j = tid; j < N; j += 256)
        if (adjcol[(size_t)j * N] != 0) list[atomicAdd(&s_cnt, 1)] = j;
    __syncthreads();
    const int cnt = s_cnt;
    const int T   = (cnt + JT - 1) / JT;

    const float* ebase = edge + ((size_t)b * N * N + i) * H;
    const float* s2b   = g_s2 + (size_t)b * N * MID;

    const int mp  = wid & 1;
    const int nq  = wid >> 1;
    const int gid = lane >> 2;
    const int tq  = lane & 3;

    float mx[4][2];
#pragma unroll
    for (int nt = 0; nt < 4; nt++) { mx[nt][0] = NEGINF; mx[nt][1] = NEGINF; }

    auto prefetch = [&](int t) {
        int off   = t * JT;
        int nrows = min(JT, cnt - off);
        float* Eb = Es  + (t & 1) * JT * ESTR;
        float* Sb = S2s + (t & 1) * JT * SSTR;
        for (int c = tid; c < JT * 32; c += 256) {
            int r = c >> 5, k4 = c & 31;
            if (r < nrows) {
                int j = list[off + r];
                cp16(smem_u32(Eb + r * ESTR + k4 * 4), ebase + (size_t)j * N * H + k4 * 4);
                cp16(smem_u32(Sb + r * SSTR + k4 * 4), s2b + (size_t)j * MID + k4 * 4);
            }
        }
        cp_commit();
    };

    if (T > 0) prefetch(0);

    for (int t = 0; t < T; t++) {
        if (t + 1 < T) { prefetch(t + 1); cp_wait<1>(); }
        else           { cp_wait<0>(); }
        __syncthreads();

        const float* Eb = Es  + (t & 1) * JT * ESTR;
        const float* Sb = S2s + (t & 1) * JT * SSTR;

        float4 acc[2][4];
#pragma unroll
        for (int mm = 0; mm < 2; mm++)
#pragma unroll
            for (int nt = 0; nt < 4; nt++)
                acc[mm][nt] = make_float4(0.f, 0.f, 0.f, 0.f);

#pragma unroll 2
        for (int ks = 0; ks < 16; ks++) {
            float a0[2], a1[2], a2[2], a3[2];
#pragma unroll
            for (int mm = 0; mm < 2; mm++) {
                int mt = mp * 2 + mm;
                const float* ap = Eb + (mt * 16 + gid) * ESTR + ks * 8 + tq;
                a0[mm] = ap[0];
                a1[mm] = ap[8 * ESTR];
                a2[mm] = ap[4];
                a3[mm] = ap[8 * ESTR + 4];
            }
#pragma unroll
            for (int nt = 0; nt < 4; nt++) {
                float2 bf = *(const float2*)(Wf + (((nq * 4 + nt) * 16 + ks) * 32 + lane) * 2);
                mma8(acc[0][nt], a0[0], a1[0], a2[0], a3[0], bf.x, bf.y);
                mma8(acc[1][nt], a0[1], a1[1], a2[1], a3[1], bf.x, bf.y);
            }
        }

        const int off = t * JT;
        const int nrows = min(JT, cnt - off);
#pragma unroll
        for (int mm = 0; mm < 2; mm++) {
            int mt = mp * 2 + mm;
            int r0 = mt * 16 + gid, r1 = r0 + 8;
            bool v0 = r0 < nrows, v1 = r1 < nrows;
#pragma unroll
            for (int nt = 0; nt < 4; nt++) {
                int col = (nq * 4 + nt) * 8 + tq * 2;
                if (v0) {
                    float2 s = *(const float2*)(Sb + r0 * SSTR + col);
                    mx[nt][0] = fmaxf(mx[nt][0], acc[mm][nt].x + s.x);
                    mx[nt][1] = fmaxf(mx[nt][1], acc[mm][nt].y + s.y);
                }
                if (v1) {
                    float2 s = *(const float2*)(Sb + r1 * SSTR + col);
                    mx[nt][0] = fmaxf(mx[nt][0], acc[mm][nt].z + s.x);
                    mx[nt][1] = fmaxf(mx[nt][1], acc[mm][nt].w + s.y);
                }
            }
        }
        __syncthreads();
    }

#pragma unroll
    for (int nt = 0; nt < 4; nt++)
#pragma unroll
        for (int cc = 0; cc < 2; cc++) {
            float v = mx[nt][cc];
            v = fmaxf(v, __shfl_xor_sync(0xffffffffu, v, 4));
            v = fmaxf(v, __shfl_xor_sync(0xffffffffu, v, 8));
            v = fmaxf(v, __shfl_xor_sync(0xffffffffu, v, 16));
            mx[nt][cc] = v;
        }
    if (gid == 0) {
#pragma unroll
        for (int nt = 0; nt < 4; nt++) {
            int col = (nq * 4 + nt) * 8 + tq * 2;
            reds[mp * 128 + col]     = mx[nt][0];
            reds[mp * 128 + col + 1] = mx[nt][1];
        }
    }
    __syncthreads();

    if (tid < MID) {
        float a;
        if (cnt == 0) {
            a = -BIGNUM;
        } else {
            float m  = fmaxf(reds[tid], reds[128 + tid]);
            float bv = g_base[((size_t)b * N + i) * MID + tid];
            a = m + bv;
            if (cnt < N) a = fmaxf(a, -BIGNUM);
        }
        g_agg[((size_t)b * N + i) * MID + tid] = a;
    }
}

// ---------------------------------------------------------------------------
// Kernel 3: output head with cp.async pipelined weights.
// 12 tiles of 32 k-rows: tiles 0-7 = Wo1 (k over z), tiles 8-11 = Wo2 (k over agg).
// ---------------------------------------------------------------------------
#define OUT_SMEM_FLOATS (16*ZD + 16*MID + 2*32*128)
#define OUT_SMEM_BYTES  (OUT_SMEM_FLOATS * 4)

__global__ __launch_bounds__(256) void out_kernel(
    const float* __restrict__ node, const float* __restrict__ hidden,
    const float* __restrict__ Wo1, const float* __restrict__ bo1,
    const float* __restrict__ Wo2, const float* __restrict__ bo2,
    float* __restrict__ out)
{
    extern __shared__ float sm[];
    float* zsm  = sm;                    // 16 * ZD
    float* agsm = zsm + 16 * ZD;         // 16 * MID
    float* Wbuf = agsm + 16 * MID;       // 2 * 32 * 128

    const int row0 = blockIdx.x * 16;
    const int tid  = threadIdx.x;

    for (int idx = tid; idx < 16 * H; idx += 256) {
        int r = idx >> 7, k = idx & 127;
        zsm[r * ZD + k]      = node  [(row0 + r) * H + k];
        zsm[r * ZD + H + k]  = hidden[(row0 + r) * H + k];
        agsm[r * MID + k]    = g_agg [(row0 + r) * MID + k];
    }

    const int q  = tid & 31;
    const int g  = tid >> 5;
    const int c4 = q * 4;

    auto pref = [&](int t) {
        const float* src = (t < 8) ? (Wo1 + t * 32 * OUTD) : (Wo2 + (t - 8) * 32 * OUTD);
        float* buf = Wbuf + (t & 1) * 32 * 128;
        for (int idx = tid; idx < 1024; idx += 256) {
            int r = idx >> 5, f = idx & 31;
            cp16(smem_u32(buf + r * 128 + f * 4), src + r * OUTD + f * 4);
        }
        cp_commit();
    };

    float4 acc[2];
#pragma unroll
    for (int r = 0; r < 2; r++) acc[r] = make_float4(0.f, 0.f, 0.f, 0.f);

    pref(0);
    __syncthreads();   // covers zsm/agsm fill

    for (int t = 0; t < 12; t++) {
        if (t < 11) { pref(t + 1); cp_wait<1>(); }
        else        { cp_wait<0>(); }
        __syncthreads();
        const float* buf = Wbuf + (t & 1) * 32 * 128;
        const float* act = (t < 8) ? (zsm + (t * 32)) : (agsm + ((t - 8) * 32));
        const int astr = (t < 8) ? ZD : MID;
#pragma unroll 4
        for (int k = 0; k < 32; k++) {
            float4 w = *(const float4*)(buf + k * 128 + c4);
#pragma unroll
            for (int r = 0; r < 2; r++) {
                float z = act[(2 * g + r) * astr + k];
                acc[r].x += z * w.x; acc[r].y += z * w.y; acc[r].z += z * w.z; acc[r].w += z * w.w;
            }
        }
        __syncthreads();
    }

    float4 b1 = *(const float4*)(bo1 + c4);
    float4 b2 = *(const float4*)(bo2 + c4);
#pragma unroll
    for (int r = 0; r < 2; r++) {
        int row = row0 + 2 * g + r;
        float4 o = make_float4(fmaxf(acc[r].x + b1.x + b2.x, 0.f),
                               fmaxf(acc[r].y + b1.y + b2.y, 0.f),
                               fmaxf(acc[r].z + b1.z + b2.z, 0.f),
                               fmaxf(acc[r].w + b1.w + b2.w, 0.f));
        *(float4*)(out + row * OUTD + c4) = o;
    }
}

// ---------------------------------------------------------------------------
extern "C" void kernel_launch(void* const* d_in, const int* in_sizes, int n_in,
                              void* d_out, int out_size)
{
    const float* node   = (const float*)d_in[0];
    const float* edge   = (const float*)d_in[1];
    const float* graph  = (const float*)d_in[2];
    const int*   adj    = (const int*)  d_in[3];
    const float* hidden = (const float*)d_in[4];
    const float* Wm1 = (const float*)d_in[5];
    const float* bm1 = (const float*)d_in[6];
    const float* Wm2 = (const float*)d_in[7];
    const float* bm2 = (const float*)d_in[8];
    const float* Wme = (const float*)d_in[9];
    const float* bme = (const float*)d_in[10];
    const float* Wmg = (const float*)d_in[11];
    const float* bmg = (const float*)d_in[12];
    const float* Wo1 = (const float*)d_in[13];
    const float* bo1 = (const float*)d_in[14];
    const float* Wo2 = (const float*)d_in[15];
    const float* bo2 = (const float*)d_in[16];
    float* out = (float*)d_out;

    static int configured = 0;
    if (!configured) {
        cudaFuncSetAttribute(msg_kernel,  cudaFuncAttributeMaxDynamicSharedMemorySize, MSG_SMEM_BYTES);
        cudaFuncSetAttribute(prep_kernel, cudaFuncAttributeMaxDynamicSharedMemorySize, PREP_SMEM_BYTES);
        cudaFuncSetAttribute(out_kernel,  cudaFuncAttributeMaxDynamicSharedMemorySize, OUT_SMEM_BYTES);
        configured = 1;
    }

    prep_kernel<<<BN / 16, 256, PREP_SMEM_BYTES>>>(node, hidden, graph,
                                                   Wm1, bm1, Wm2, bm2, Wmg, bmg, bme);
    msg_kernel<<<BN, 256, MSG_SMEM_BYTES>>>(edge, adj, Wme);
    out_kernel<<<BN / 16, 256, OUT_SMEM_BYTES>>>(node, hidden, Wo1, bo1, Wo2, bo2, out);
}